// round 1
// baseline (speedup 1.0000x reference)
#include <cuda_runtime.h>

// InversePoseMatrixLayer: out = [R^T | -R^T t] for 4M poses, each 3x4 row-major fp32.
// Pure streaming kernel: 48B in + 48B out per pose, HBM-bound.
// Each thread: 3x LDG.128 + 9 FMA + 3x STG.128. 48B pose stride is 16B-aligned,
// so float4 vector access is legal everywhere.

__global__ __launch_bounds__(256) void inverse_pose_kernel(
    const float4* __restrict__ in, float4* __restrict__ out, int n_poses)
{
    int b = blockIdx.x * blockDim.x + threadIdx.x;
    if (b >= n_poses) return;

    const float4 r0 = in[3 * b + 0];  // (R00, R01, R02, t0)
    const float4 r1 = in[3 * b + 1];  // (R10, R11, R12, t1)
    const float4 r2 = in[3 * b + 2];  // (R20, R21, R22, t2)

    // t_inv = -R^T t
    const float ti0 = -(r0.x * r0.w + r1.x * r1.w + r2.x * r2.w);
    const float ti1 = -(r0.y * r0.w + r1.y * r1.w + r2.y * r2.w);
    const float ti2 = -(r0.z * r0.w + r1.z * r1.w + r2.z * r2.w);

    out[3 * b + 0] = make_float4(r0.x, r1.x, r2.x, ti0);
    out[3 * b + 1] = make_float4(r0.y, r1.y, r2.y, ti1);
    out[3 * b + 2] = make_float4(r0.z, r1.z, r2.z, ti2);
}

extern "C" void kernel_launch(void* const* d_in, const int* in_sizes, int n_in,
                              void* d_out, int out_size)
{
    const float4* in = (const float4*)d_in[0];
    float4* out = (float4*)d_out;
    const int n_poses = in_sizes[0] / 12;   // 12 floats per pose

    const int threads = 256;
    const int blocks = (n_poses + threads - 1) / threads;
    inverse_pose_kernel<<<blocks, threads>>>(in, out, n_poses);
}

// round 2
// speedup vs baseline: 1.0162x; 1.0162x over previous
#include <cuda_runtime.h>

// InversePoseMatrixLayer: out = [R^T | -R^T t] for 4M poses (3x4 fp32 each).
//
// R1 change: shared-memory staging so ALL global traffic is unit-stride
// (4 lines per 128b access, no L1 wavefront replays). The 48B-stride
// transpose gather/scatter happens in smem, where the stride-3-float4
// access pattern is bank-conflict-free (per 8-lane phase, start banks
// {0,12,24,4,16,28,8,20} tile all 32 banks exactly once).

#define POSES_PER_BLOCK 256
#define VEC_PER_BLOCK   (POSES_PER_BLOCK * 3)   // float4s per block

__global__ __launch_bounds__(POSES_PER_BLOCK) void inverse_pose_kernel(
    const float4* __restrict__ in, float4* __restrict__ out, int n_poses)
{
    __shared__ float4 s[VEC_PER_BLOCK];

    const int tid      = threadIdx.x;
    const int vec_base = blockIdx.x * VEC_PER_BLOCK;   // float4 index of block start
    const int n_vec    = n_poses * 3;

    // Phase 1: coalesced global -> smem (unit stride across lanes)
    #pragma unroll
    for (int k = 0; k < 3; k++) {
        int idx = vec_base + k * POSES_PER_BLOCK + tid;
        if (idx < n_vec)
            s[k * POSES_PER_BLOCK + tid] = in[idx];
    }
    __syncthreads();

    // Phase 2: per-thread pose inverse entirely in smem-local slots.
    // Thread i reads and writes only slots {3i, 3i+1, 3i+2} -> no race.
    const int p = blockIdx.x * POSES_PER_BLOCK + tid;
    if (p < n_poses) {
        const float4 r0 = s[3 * tid + 0];   // (R00, R01, R02, t0)
        const float4 r1 = s[3 * tid + 1];   // (R10, R11, R12, t1)
        const float4 r2 = s[3 * tid + 2];   // (R20, R21, R22, t2)

        const float ti0 = -(r0.x * r0.w + r1.x * r1.w + r2.x * r2.w);
        const float ti1 = -(r0.y * r0.w + r1.y * r1.w + r2.y * r2.w);
        const float ti2 = -(r0.z * r0.w + r1.z * r1.w + r2.z * r2.w);

        s[3 * tid + 0] = make_float4(r0.x, r1.x, r2.x, ti0);
        s[3 * tid + 1] = make_float4(r0.y, r1.y, r2.y, ti1);
        s[3 * tid + 2] = make_float4(r0.z, r1.z, r2.z, ti2);
    }
    __syncthreads();

    // Phase 3: coalesced smem -> global (unit stride across lanes)
    #pragma unroll
    for (int k = 0; k < 3; k++) {
        int idx = vec_base + k * POSES_PER_BLOCK + tid;
        if (idx < n_vec)
            out[idx] = s[k * POSES_PER_BLOCK + tid];
    }
}

extern "C" void kernel_launch(void* const* d_in, const int* in_sizes, int n_in,
                              void* d_out, int out_size)
{
    const float4* in = (const float4*)d_in[0];
    float4* out = (float4*)d_out;
    const int n_poses = in_sizes[0] / 12;   // 12 floats per pose

    const int blocks = (n_poses + POSES_PER_BLOCK - 1) / POSES_PER_BLOCK;
    inverse_pose_kernel<<<blocks, POSES_PER_BLOCK>>>(in, out, n_poses);
}